// round 5
// baseline (speedup 1.0000x reference)
#include <cuda_runtime.h>
#include <cstdint>

#define H      512
#define EPB    8

// ---------------- scratch: transposed loop weight, tf32-rounded ----------------
__device__ unsigned int g_Bt[H * H];   // Bt[n][k] = tf32(lw[k][n]) bit pattern

__device__ __forceinline__ unsigned int f2tf32(float f) {
    unsigned int u;
    asm("cvt.rna.tf32.f32 %0, %1;" : "=r"(u) : "f"(f));
    return u;
}
__device__ __forceinline__ uint32_t smem_u32(const void* p) {
    uint32_t a;
    asm("{ .reg .u64 t; cvta.to.shared.u64 t, %1; cvt.u32.u64 %0, t; }" : "=r"(a) : "l"(p));
    return a;
}
__device__ __forceinline__ void cp_async16(void* sptr, const void* gptr) {
    asm volatile("cp.async.cg.shared.global [%0], [%1], 16;"
                 :: "r"(smem_u32(sptr)), "l"(gptr));
}
__device__ __forceinline__ void red4(float* p, float4 v) {
    asm volatile("red.global.add.v4.f32 [%0], {%1, %2, %3, %4};"
                 :: "l"(p), "f"(v.x), "f"(v.y), "f"(v.z), "f"(v.w) : "memory");
}
__device__ __forceinline__ void red2(float* p, float a, float b) {
    asm volatile("red.global.add.v2.f32 [%0], {%1, %2};"
                 :: "l"(p), "f"(a), "f"(b) : "memory");
}

// ---------------- transpose 512x512 + tf32 round ----------------
__global__ void transpose512(const float* __restrict__ lw) {
    __shared__ float t[32][33];
    const int bx = blockIdx.x * 32, by = blockIdx.y * 32;
#pragma unroll
    for (int j = 0; j < 4; j++)
        t[threadIdx.y + 8 * j][threadIdx.x] =
            lw[(by + threadIdx.y + 8 * j) * H + bx + threadIdx.x];
    __syncthreads();
#pragma unroll
    for (int j = 0; j < 4; j++)
        g_Bt[(bx + threadIdx.y + 8 * j) * H + by + threadIdx.x] =
            f2tf32(t[threadIdx.x][threadIdx.y + 8 * j]);
}

// ---------------- fused heterogeneous kernel ----------------
// GEMM tiles 128x64 (8 N-tiles per M block, adjacent in grid order -> A L2 reuse),
// warp tile 32x32, cp.async for B, double-buffered. Edge blocks interleaved
// proportionally so every SM mixes tensor-bound and L1-bound work.
// out must be pre-zeroed.
#define BK     16
#define LDS_S  20
#define A_FL   (128 * LDS_S)
#define B_FL   (64 * LDS_S)

__global__ __launch_bounds__(256, 3)
void fused_kernel(const float* __restrict__ A, const float* __restrict__ bias,
                  const void* __restrict__ srcv, const void* __restrict__ dstv,
                  const void* __restrict__ etv, const float* __restrict__ norm,
                  const float* __restrict__ wt,
                  float* __restrict__ out, int M, int E, int GB, int TOT)
{
    const int tid  = threadIdx.x;
    const int wid  = tid >> 5;
    const int lane = tid & 31;

    const long long bid = blockIdx.x;
    const long long g   = bid * GB / TOT;
    const bool is_gemm  = ((bid + 1) * GB / TOT) > g;

    if (is_gemm) {
        // ================= GEMM part: tile 128x64 =================
        __shared__ unsigned int As[2][A_FL];
        __shared__ unsigned int Bs[2][B_FL];

        const int tile = (int)g;
        const int bm   = (tile >> 3) * 128;
        const int bn   = (tile & 7) * 64;
        const int l4   = lane >> 2;
        const int lm   = lane & 3;
        const int wm0  = (wid & 3) * 32;
        const int wn0  = (wid >> 2) * 32;

        float acc[2][4][4];
#pragma unroll
        for (int i = 0; i < 2; i++)
#pragma unroll
            for (int j = 0; j < 4; j++)
#pragma unroll
                for (int q = 0; q < 4; q++) acc[i][j][q] = 0.f;

        // A: 512 float4 per tile -> 2 per thread
        const int a_row0 = tid >> 2, a_kq0 = tid & 3;            // i=0
        const int a_row1 = (tid + 256) >> 2, a_kq1 = tid & 3;    // i=1
        float4 stA[2];

        auto load_A = [&](int kt) {
            stA[0] = make_float4(0.f, 0.f, 0.f, 0.f);
            stA[1] = make_float4(0.f, 0.f, 0.f, 0.f);
            if (bm + a_row0 < M)
                stA[0] = *(const float4*)(A + (size_t)(bm + a_row0) * H + kt + a_kq0 * 4);
            if (bm + a_row1 < M)
                stA[1] = *(const float4*)(A + (size_t)(bm + a_row1) * H + kt + a_kq1 * 4);
        };
        auto store_A = [&](int b) {
            uint4 v;
            v.x = f2tf32(stA[0].x); v.y = f2tf32(stA[0].y);
            v.z = f2tf32(stA[0].z); v.w = f2tf32(stA[0].w);
            *(uint4*)&As[b][a_row0 * LDS_S + a_kq0 * 4] = v;
            v.x = f2tf32(stA[1].x); v.y = f2tf32(stA[1].y);
            v.z = f2tf32(stA[1].z); v.w = f2tf32(stA[1].w);
            *(uint4*)&As[b][a_row1 * LDS_S + a_kq1 * 4] = v;
        };
        // B: 64 rows x 4 chunks = 256 cp.async, 1 per thread
        const int b_row = tid >> 2, b_kq = tid & 3;
        auto issue_B = [&](int kt, int b) {
            cp_async16(&Bs[b][b_row * LDS_S + b_kq * 4],
                       (const float*)g_Bt + (size_t)(bn + b_row) * H + kt + b_kq * 4);
            asm volatile("cp.async.commit_group;");
        };

        load_A(0);
        issue_B(0, 0);
        store_A(0);
        asm volatile("cp.async.wait_group 0;");
        __syncthreads();

        const int NK = H / BK;   // 32
        for (int kt = 0; kt < NK; kt++) {
            const int b = kt & 1;
            if (kt + 1 < NK) {
                load_A((kt + 1) * BK);
                issue_B((kt + 1) * BK, b ^ 1);
            }

#pragma unroll
            for (int ks = 0; ks < 2; ks++) {
                const int k8 = ks * 8;
                unsigned int af[2][4];
#pragma unroll
                for (int mt = 0; mt < 2; mt++) {
                    const int rm = wm0 + mt * 16 + l4;
                    af[mt][0] = As[b][rm * LDS_S + k8 + lm];
                    af[mt][1] = As[b][(rm + 8) * LDS_S + k8 + lm];
                    af[mt][2] = As[b][rm * LDS_S + k8 + lm + 4];
                    af[mt][3] = As[b][(rm + 8) * LDS_S + k8 + lm + 4];
                }
#pragma unroll
                for (int nt = 0; nt < 4; nt++) {
                    const int cn = wn0 + nt * 8 + l4;
                    const unsigned int b0 = Bs[b][cn * LDS_S + k8 + lm];
                    const unsigned int b1 = Bs[b][cn * LDS_S + k8 + lm + 4];
#pragma unroll
                    for (int mt = 0; mt < 2; mt++) {
                        asm volatile(
                            "mma.sync.aligned.m16n8k8.row.col.f32.tf32.tf32.f32 "
                            "{%0,%1,%2,%3}, {%4,%5,%6,%7}, {%8,%9}, {%0,%1,%2,%3};"
                            : "+f"(acc[mt][nt][0]), "+f"(acc[mt][nt][1]),
                              "+f"(acc[mt][nt][2]), "+f"(acc[mt][nt][3])
                            : "r"(af[mt][0]), "r"(af[mt][1]), "r"(af[mt][2]), "r"(af[mt][3]),
                              "r"(b0), "r"(b1));
                    }
                }
            }

            if (kt + 1 < NK) store_A(b ^ 1);
            asm volatile("cp.async.wait_group 0;");
            __syncthreads();
        }

        // epilogue: atomic accumulate (+bias once per element)
#pragma unroll
        for (int mt = 0; mt < 2; mt++) {
            const int r0 = bm + wm0 + mt * 16 + l4;
            const int r1 = r0 + 8;
#pragma unroll
            for (int nt = 0; nt < 4; nt++) {
                const int c = bn + wn0 + nt * 8 + lm * 2;
                const float b0 = bias[c], b1 = bias[c + 1];
                if (r0 < M) red2(out + (size_t)r0 * H + c,
                                 acc[mt][nt][0] + b0, acc[mt][nt][1] + b1);
                if (r1 < M) red2(out + (size_t)r1 * H + c,
                                 acc[mt][nt][2] + b0, acc[mt][nt][3] + b1);
            }
        }
    } else {
        // ================= edge part =================
        __shared__ int is64;
        if (tid == 0) {
            const int* s = (const int*)srcv;
            int orv = 0;
#pragma unroll
            for (int j = 0; j < 32; j++) orv |= s[2 * j + 1];
            is64 = (orv == 0) ? 1 : 0;
        }
        __syncthreads();

        const int eblk = (int)(bid - g);
        const int e = eblk * EPB + wid;
        if (e >= E) return;

        long long s, d, t;
        if (is64) {
            s = ((const long long*)srcv)[e];
            d = ((const long long*)dstv)[e];
            t = ((const long long*)etv)[e];
        } else {
            s = ((const int*)srcv)[e];
            d = ((const int*)dstv)[e];
            t = ((const int*)etv)[e];
        }
        const float nr = norm[e];

        const float4* h4 = (const float4*)(A + (size_t)s * H) + lane * 4;
        const float4* w4 = (const float4*)(wt + (size_t)t * 2048) + lane * 16;
        float* obase     = out + (size_t)d * H + lane * 16;

        float4 hv[4];
#pragma unroll
        for (int jb = 0; jb < 4; jb++) hv[jb] = h4[jb];

#pragma unroll
        for (int jb = 0; jb < 4; jb++) {
            const float4 w0 = w4[jb * 4 + 0];
            const float4 w1 = w4[jb * 4 + 1];
            const float4 w2 = w4[jb * 4 + 2];
            const float4 w3 = w4[jb * 4 + 3];
            const float4 h  = hv[jb];
            float4 m;
            m.x = fmaf(h.w, w3.x, fmaf(h.z, w2.x, fmaf(h.y, w1.x, h.x * w0.x)));
            m.y = fmaf(h.w, w3.y, fmaf(h.z, w2.y, fmaf(h.y, w1.y, h.x * w0.y)));
            m.z = fmaf(h.w, w3.z, fmaf(h.z, w2.z, fmaf(h.y, w1.z, h.x * w0.z)));
            m.w = fmaf(h.w, w3.w, fmaf(h.z, w2.w, fmaf(h.y, w1.w, h.x * w0.w)));
            m.x *= nr; m.y *= nr; m.z *= nr; m.w *= nr;
            red4(obase + jb * 4, m);
        }
    }
}

// ---------------- launch ----------------
extern "C" void kernel_launch(void* const* d_in, const int* in_sizes, int n_in,
                              void* d_out, int out_size)
{
    // 0=node_ids (arange, unused), 1=src, 2=dst, 3=etypes, 4=norm,
    // 5=emb, 6=weight, 7=loop_weight, 8=bias
    const float* norm = (const float*)d_in[4];
    const float* emb  = (const float*)d_in[5];
    const float* wt   = (const float*)d_in[6];
    const float* lw   = (const float*)d_in[7];
    const float* bias = (const float*)d_in[8];
    float* out = (float*)d_out;

    const int M = in_sizes[5] / H;
    const int E = in_sizes[1];

    transpose512<<<dim3(16, 16), dim3(32, 8)>>>(lw);

    cudaMemsetAsync(d_out, 0, (size_t)out_size * sizeof(float));

    const int GB  = ((M + 127) / 128) * 8;   // 128x64 gemm tiles
    const int EB  = (E + EPB - 1) / EPB;     // edge blocks
    const int TOT = GB + EB;
    fused_kernel<<<TOT, 256>>>(emb, bias, d_in[1], d_in[2], d_in[3],
                               norm, wt, out, M, E, GB, TOT);
}

// round 6
// speedup vs baseline: 1.1432x; 1.1432x over previous
#include <cuda_runtime.h>
#include <cstdint>

#define H      512
#define EPB    8

// ---------------- scratch: transposed loop weight, tf32-rounded ----------------
__device__ unsigned int g_Bt[H * H];   // Bt[n][k] = tf32(lw[k][n]) bit pattern

__device__ __forceinline__ unsigned int f2tf32(float f) {
    unsigned int u;
    asm("cvt.rna.tf32.f32 %0, %1;" : "=r"(u) : "f"(f));
    return u;
}
__device__ __forceinline__ void red4(float* p, float4 v) {
    asm volatile("red.global.add.v4.f32 [%0], {%1, %2, %3, %4};"
                 :: "l"(p), "f"(v.x), "f"(v.y), "f"(v.z), "f"(v.w) : "memory");
}
__device__ __forceinline__ void red2(float* p, float a, float b) {
    asm volatile("red.global.add.v2.f32 [%0], {%1, %2};"
                 :: "l"(p), "f"(a), "f"(b) : "memory");
}

// ---------------- transpose 512x512 + tf32 round ----------------
__global__ void transpose512(const float* __restrict__ lw) {
    __shared__ float t[32][33];
    const int bx = blockIdx.x * 32, by = blockIdx.y * 32;
#pragma unroll
    for (int j = 0; j < 4; j++)
        t[threadIdx.y + 8 * j][threadIdx.x] =
            lw[(by + threadIdx.y + 8 * j) * H + bx + threadIdx.x];
    __syncthreads();
#pragma unroll
    for (int j = 0; j < 4; j++)
        g_Bt[(bx + threadIdx.y + 8 * j) * H + by + threadIdx.x] =
            f2tf32(t[threadIdx.x][threadIdx.y + 8 * j]);
}

// ---------------- fused heterogeneous kernel ----------------
// GEMM: R4 config — 128x128 tile, warp tile 32x64, double-buffered smem.
// Edge: coalesced remap — quad-per-base, butterfly reduce, coalesced red.v4.
// Blocks interleaved proportionally. out must be pre-zeroed.
#define BK     16
#define LDS_S  20
#define BUFSZ  (128 * LDS_S)

__global__ __launch_bounds__(256)
void fused_kernel(const float* __restrict__ A, const float* __restrict__ bias,
                  const void* __restrict__ srcv, const void* __restrict__ dstv,
                  const void* __restrict__ etv, const float* __restrict__ norm,
                  const float* __restrict__ wt,
                  float* __restrict__ out, int M, int E, int GB, int TOT)
{
    const int tid  = threadIdx.x;
    const int wid  = tid >> 5;
    const int lane = tid & 31;

    const long long bid = blockIdx.x;
    const long long g   = bid * GB / TOT;
    const bool is_gemm  = ((bid + 1) * GB / TOT) > g;

    if (is_gemm) {
        // ================= GEMM part (R4 config) =================
        __shared__ unsigned int As[2][BUFSZ];
        __shared__ unsigned int Bs[2][BUFSZ];

        const int tile = (int)g;
        const int l4  = lane >> 2;
        const int lm  = lane & 3;
        const int bm  = (tile >> 2) * 128;
        const int bn  = (tile & 3) * 128;
        const int wm0 = (wid & 3) * 32;
        const int wn0 = (wid >> 2) * 64;

        float acc[2][8][4];
#pragma unroll
        for (int i = 0; i < 2; i++)
#pragma unroll
            for (int j = 0; j < 8; j++)
#pragma unroll
                for (int q = 0; q < 4; q++) acc[i][j][q] = 0.f;

        float4 stA[2], stB[2];
        auto load_regs = [&](int kt) {
#pragma unroll
            for (int i = 0; i < 2; i++) {
                const int f4 = tid + i * 256;
                const int row = f4 >> 2, kq = f4 & 3;
                const int gm = bm + row;
                stA[i] = make_float4(0.f, 0.f, 0.f, 0.f);
                if (gm < M) stA[i] = *(const float4*)(A + (size_t)gm * H + kt + kq * 4);
                stB[i] = *(const float4*)((const float*)g_Bt + (size_t)(bn + row) * H + kt + kq * 4);
            }
        };
        auto store_smem = [&](int b) {
#pragma unroll
            for (int i = 0; i < 2; i++) {
                const int f4 = tid + i * 256;
                const int row = f4 >> 2, kq = f4 & 3;
                uint4 av;
                av.x = f2tf32(stA[i].x); av.y = f2tf32(stA[i].y);
                av.z = f2tf32(stA[i].z); av.w = f2tf32(stA[i].w);
                *(uint4*)&As[b][row * LDS_S + kq * 4] = av;
                uint4 bv;
                bv.x = __float_as_uint(stB[i].x); bv.y = __float_as_uint(stB[i].y);
                bv.z = __float_as_uint(stB[i].z); bv.w = __float_as_uint(stB[i].w);
                *(uint4*)&Bs[b][row * LDS_S + kq * 4] = bv;
            }
        };

        load_regs(0);
        store_smem(0);
        __syncthreads();

        const int NK = H / BK;
        for (int kt = 0; kt < NK; kt++) {
            if (kt + 1 < NK) load_regs((kt + 1) * BK);

            const int b = kt & 1;
#pragma unroll
            for (int ks = 0; ks < 2; ks++) {
                const int k8 = ks * 8;
                unsigned int af[2][4];
#pragma unroll
                for (int mt = 0; mt < 2; mt++) {
                    const int rm = wm0 + mt * 16 + l4;
                    af[mt][0] = As[b][rm * LDS_S + k8 + lm];
                    af[mt][1] = As[b][(rm + 8) * LDS_S + k8 + lm];
                    af[mt][2] = As[b][rm * LDS_S + k8 + lm + 4];
                    af[mt][3] = As[b][(rm + 8) * LDS_S + k8 + lm + 4];
                }
#pragma unroll
                for (int nt = 0; nt < 8; nt++) {
                    const int cn = wn0 + nt * 8 + l4;
                    const unsigned int b0 = Bs[b][cn * LDS_S + k8 + lm];
                    const unsigned int b1 = Bs[b][cn * LDS_S + k8 + lm + 4];
#pragma unroll
                    for (int mt = 0; mt < 2; mt++) {
                        asm volatile(
                            "mma.sync.aligned.m16n8k8.row.col.f32.tf32.tf32.f32 "
                            "{%0,%1,%2,%3}, {%4,%5,%6,%7}, {%8,%9}, {%0,%1,%2,%3};"
                            : "+f"(acc[mt][nt][0]), "+f"(acc[mt][nt][1]),
                              "+f"(acc[mt][nt][2]), "+f"(acc[mt][nt][3])
                            : "r"(af[mt][0]), "r"(af[mt][1]), "r"(af[mt][2]), "r"(af[mt][3]),
                              "r"(b0), "r"(b1));
                    }
                }
            }

            if (kt + 1 < NK) store_smem((kt + 1) & 1);
            __syncthreads();
        }

        // epilogue: atomic accumulate (+bias once per element)
#pragma unroll
        for (int mt = 0; mt < 2; mt++) {
            const int r0 = bm + wm0 + mt * 16 + l4;
            const int r1 = r0 + 8;
#pragma unroll
            for (int nt = 0; nt < 8; nt++) {
                const int c = bn + wn0 + nt * 8 + lm * 2;
                const float b0 = bias[c], b1 = bias[c + 1];
                if (r0 < M) red2(out + (size_t)r0 * H + c,
                                 acc[mt][nt][0] + b0, acc[mt][nt][1] + b1);
                if (r1 < M) red2(out + (size_t)r1 * H + c,
                                 acc[mt][nt][2] + b0, acc[mt][nt][3] + b1);
            }
        }
    } else {
        // ================= edge part: coalesced quad-per-base =================
        __shared__ int is64;
        if (tid == 0) {
            const int* s = (const int*)srcv;
            int orv = 0;
#pragma unroll
            for (int j = 0; j < 32; j++) orv |= s[2 * j + 1];
            is64 = (orv == 0) ? 1 : 0;
        }
        __syncthreads();

        const int e = (int)(bid - g) * EPB + wid;
        if (e >= E) return;

        long long s, d, t;
        if (is64) {
            s = ((const long long*)srcv)[e];
            d = ((const long long*)dstv)[e];
            t = ((const long long*)etv)[e];
        } else {
            s = ((const int*)srcv)[e];
            d = ((const int*)dstv)[e];
            t = ((const int*)etv)[e];
        }
        const float nr = norm[e];

        // lane = (g=lane>>2, i=lane&3). Pass p covers bases p*8 .. p*8+7.
        // Weight read: lane -> w[base=p*8+g][i][0..3], warp-contiguous 512B.
        const float4* wbase = (const float4*)(wt + (size_t)t * 2048) + lane;
        const float*  hbase = A + (size_t)s * H + lane;
        float* obase        = out + (size_t)d * H + (lane >> 2) * 4;
        const bool writer   = (lane & 3) == 0;

#pragma unroll 4
        for (int p = 0; p < 16; p++) {
            const float4 w = wbase[p * 32];          // coalesced 512B per warp
            const float hv = hbase[p * 32];          // coalesced 128B per warp
            float4 m = make_float4(hv * w.x, hv * w.y, hv * w.z, hv * w.w);
            // reduce over i (quad butterfly)
            m.x += __shfl_xor_sync(0xFFFFFFFFu, m.x, 1);
            m.y += __shfl_xor_sync(0xFFFFFFFFu, m.y, 1);
            m.z += __shfl_xor_sync(0xFFFFFFFFu, m.z, 1);
            m.w += __shfl_xor_sync(0xFFFFFFFFu, m.w, 1);
            m.x += __shfl_xor_sync(0xFFFFFFFFu, m.x, 2);
            m.y += __shfl_xor_sync(0xFFFFFFFFu, m.y, 2);
            m.z += __shfl_xor_sync(0xFFFFFFFFu, m.z, 2);
            m.w += __shfl_xor_sync(0xFFFFFFFFu, m.w, 2);
            if (writer) {
                m.x *= nr; m.y *= nr; m.z *= nr; m.w *= nr;
                red4(obase + p * 32, m);             // 8 lanes, contiguous 128B
            }
        }
    }
}

// ---------------- launch ----------------
extern "C" void kernel_launch(void* const* d_in, const int* in_sizes, int n_in,
                              void* d_out, int out_size)
{
    // 0=node_ids (arange, unused), 1=src, 2=dst, 3=etypes, 4=norm,
    // 5=emb, 6=weight, 7=loop_weight, 8=bias
    const float* norm = (const float*)d_in[4];
    const float* emb  = (const float*)d_in[5];
    const float* wt   = (const float*)d_in[6];
    const float* lw   = (const float*)d_in[7];
    const float* bias = (const float*)d_in[8];
    float* out = (float*)d_out;

    const int M = in_sizes[5] / H;
    const int E = in_sizes[1];

    transpose512<<<dim3(16, 16), dim3(32, 8)>>>(lw);

    cudaMemsetAsync(d_out, 0, (size_t)out_size * sizeof(float));

    const int GB  = ((M + 127) / 128) * 4;   // 128x128 gemm tiles
    const int EB  = (E + EPB - 1) / EPB;     // edge blocks
    const int TOT = GB + EB;
    fused_kernel<<<TOT, 256>>>(emb, bias, d_in[1], d_in[2], d_in[3],
                               norm, wt, out, M, E, GB, TOT);
}